// round 9
// baseline (speedup 1.0000x reference)
#include <cuda_runtime.h>

// Conv2D valid cross-correlation: x[4096,4096] fp32 * w[15,15] + bias -> out[4082,4082]
//
// v8: issue-slot reduction. The kernel is issue-bound (fma% == FFMA2 share of
//     total issues across v4/v5/v7). Cut the biggest aux bucket: weight loads.
//  - weights in __constant__, loaded as 16B ulonglong2 (LDCU.128): 8 loads per
//    conv_row instead of 15. Row parity (15r odd/even) handled by conv_row<P>
//    template; steady loop unrolled x2 so parity is compile-time.
//  - __launch_bounds__(256,4): undo v7's reg squeeze (48 regs -> spills, L2 2x).
//  - RY=4 tile (128x * 64y per block, 8x * 4y per thread), SSTR=144.

#define Hd 4096
#define Wd 4096
#define KHd 15
#define KWd 15
#define OHd (Hd - KHd + 1)   // 4082
#define OWd (Wd - KWd + 1)   // 4082

#define BXo 128
#define BYo 64
#define RY 4
#define TILE_ROWS (BYo + KHd - 1)   // 78
#define SSTR 144                     // floats per smem row

typedef unsigned long long u64;

// (w,w) duplicated pairs, rows contiguous (15 u64 per row), padded to 240 so
// the aligned-window pair loads (which touch one element past row 14) are safe.
__constant__ __align__(16) u64 c_w2[240];

__device__ __forceinline__ u64 pack2(float lo, float hi) {
    u64 r;
    asm("mov.b64 %0, {%1, %2};" : "=l"(r) : "f"(lo), "f"(hi));
    return r;
}

__device__ __forceinline__ u64 fma2(u64 a, u64 b, u64 c) {
    u64 d;
    asm("fma.rn.f32x2 %0, %1, %2, %3;" : "=l"(d) : "l"(a), "l"(b), "l"(c));
    return d;
}

// odd pair = {hi(a), lo(b)} : exactly 2 SASS MOVs
__device__ __forceinline__ u64 mkodd(u64 a, u64 b) {
    u64 r;
    asm("{\n\t"
        ".reg .b32 al, ah, bl, bh;\n\t"
        "mov.b64 {al, ah}, %1;\n\t"
        "mov.b64 {bl, bh}, %2;\n\t"
        "mov.b64 %0, {ah, bl};\n\t"
        "}" : "=l"(r) : "l"(a), "l"(b));
    return r;
}

// 16B-aligned pair-load base for weight row `row` (parity P == row & 1):
//   P=0: q[i] = (w[2i], w[2i+1])        i = 0..7 (q[7].y is padding, unused)
//   P=1: q[i] = (w[2i-1], w[2i])        i = 0..7 (q[0].x is prev row, unused)
__device__ __forceinline__ const ulonglong2* qrow(int row) {
    return (const ulonglong2*)(c_w2 + 15 * row - (row & 1));
}

// One ky-row of the stencil applied to 4 output pairs of one output row.
template<int P>
__device__ __forceinline__ void conv_row(u64 acc[4],
                                         const ulonglong2* __restrict__ q,
                                         const u64 ev[12],
                                         const u64 od[10]) {
#pragma unroll
    for (int i = 0; i < 8; ++i) {
        ulonglong2 w = q[i];   // uniform 16B cmem load
        if (P == 0) {
            // even kx = 2i ; odd kx = 2i+1
#pragma unroll
            for (int p = 0; p < 4; ++p)
                acc[p] = fma2(ev[i + p], w.x, acc[p]);
            if (i < 7) {
#pragma unroll
                for (int p = 0; p < 4; ++p)
                    acc[p] = fma2(od[i + p], w.y, acc[p]);
            }
        } else {
            // even kx = 2i (w.y) ; odd kx = 2i-1 (w.x, valid for i >= 1)
#pragma unroll
            for (int p = 0; p < 4; ++p)
                acc[p] = fma2(ev[i + p], w.y, acc[p]);
            if (i >= 1) {
#pragma unroll
                for (int p = 0; p < 4; ++p)
                    acc[p] = fma2(od[i - 1 + p], w.x, acc[p]);
            }
        }
    }
}

// Load 12 even pairs (direct ulonglong2) and derive 10 odd pairs (2 MOVs each).
__device__ __forceinline__ void load_row(const float* __restrict__ srow,
                                         u64 ev[12], u64 od[10]) {
#pragma unroll
    for (int i = 0; i < 6; ++i) {
        ulonglong2 v = ((const ulonglong2*)srow)[i];
        ev[2 * i + 0] = v.x;
        ev[2 * i + 1] = v.y;
    }
#pragma unroll
    for (int j = 0; j < 10; ++j)
        od[j] = mkodd(ev[j], ev[j + 1]);
}

__global__ __launch_bounds__(256, 4)
void conv2d_f32x2_kernel(const float* __restrict__ x,
                         const float* __restrict__ bias,
                         float* __restrict__ out) {
    __shared__ float s_in[TILE_ROWS * SSTR];   // 78*144*4 = 44928 B

    const int tid = threadIdx.x;
    const int tx0 = blockIdx.x * BXo;
    const int ty0 = blockIdx.y * BYo;

    // Stage input tile: 78 rows x 144 floats.
    for (int s = tid; s < TILE_ROWS * 36; s += 256) {
        int rr = s / 36;
        int cc = (s - rr * 36) * 4;
        int gy = ty0 + rr;
        int gx = tx0 + cc;
        float4 v;
        if (gy < Hd && gx + 3 < Wd) {
            v = *(const float4*)(x + (size_t)gy * Wd + gx);
        } else {
            v.x = (gy < Hd && gx + 0 < Wd) ? x[(size_t)gy * Wd + gx + 0] : 0.f;
            v.y = (gy < Hd && gx + 1 < Wd) ? x[(size_t)gy * Wd + gx + 1] : 0.f;
            v.z = (gy < Hd && gx + 2 < Wd) ? x[(size_t)gy * Wd + gx + 2] : 0.f;
            v.w = (gy < Hd && gx + 3 < Wd) ? x[(size_t)gy * Wd + gx + 3] : 0.f;
        }
        *(float4*)&s_in[rr * SSTR + cc] = v;
    }
    __syncthreads();

    const int tx = tid & 15;
    const int ty = tid >> 4;
    const int oxl = tx * 8;        // 8 outputs in x
    const int oyl = ty * RY;       // 4 outputs in y

    const float b = bias[0];
    const u64 b2 = pack2(b, b);
    u64 acc[RY][4];
#pragma unroll
    for (int j = 0; j < RY; ++j)
#pragma unroll
        for (int p = 0; p < 4; ++p) acc[j][p] = b2;

    u64 ev[12], od[10];
    const float* sbase = &s_in[oyl * SSTR + oxl];

    // Prologue: r = 0,1,2  (weight-row parities: 15r & 1 == r & 1)
    load_row(sbase + 0 * SSTR, ev, od);
    conv_row<0>(acc[0], qrow(0), ev, od);

    load_row(sbase + 1 * SSTR, ev, od);
    conv_row<1>(acc[0], qrow(1), ev, od);
    conv_row<0>(acc[1], qrow(0), ev, od);

    load_row(sbase + 2 * SSTR, ev, od);
    conv_row<0>(acc[0], qrow(2), ev, od);
    conv_row<1>(acc[1], qrow(1), ev, od);
    conv_row<0>(acc[2], qrow(0), ev, od);

    // Steady: r = 3..14, unrolled x2 so weight-row parity is compile-time.
#pragma unroll 1
    for (int r = 3; r + 1 < KHd; r += 2) {
        // r odd
        load_row(sbase + r * SSTR, ev, od);
        conv_row<1>(acc[0], qrow(r),     ev, od);
        conv_row<0>(acc[1], qrow(r - 1), ev, od);
        conv_row<1>(acc[2], qrow(r - 2), ev, od);
        conv_row<0>(acc[3], qrow(r - 3), ev, od);
        // r+1 even
        load_row(sbase + (r + 1) * SSTR, ev, od);
        conv_row<0>(acc[0], qrow(r + 1), ev, od);
        conv_row<1>(acc[1], qrow(r),     ev, od);
        conv_row<0>(acc[2], qrow(r - 1), ev, od);
        conv_row<1>(acc[3], qrow(r - 2), ev, od);
    }

    // Epilogue: r = 15,16,17
    load_row(sbase + 15 * SSTR, ev, od);
    conv_row<0>(acc[1], qrow(14), ev, od);
    conv_row<1>(acc[2], qrow(13), ev, od);
    conv_row<0>(acc[3], qrow(12), ev, od);

    load_row(sbase + 16 * SSTR, ev, od);
    conv_row<0>(acc[2], qrow(14), ev, od);
    conv_row<1>(acc[3], qrow(13), ev, od);

    load_row(sbase + 17 * SSTR, ev, od);
    conv_row<0>(acc[3], qrow(14), ev, od);

    // Store: even-aligned 8B pairs; OW=4082 even -> pairs never straddle rows.
    const int oxg = tx0 + oxl;
#pragma unroll
    for (int j = 0; j < RY; ++j) {
        int oy = ty0 + oyl + j;
        if (oy < OHd) {
            float* orow = out + (size_t)oy * OWd;
#pragma unroll
            for (int p = 0; p < 4; ++p) {
                int ox = oxg + 2 * p;
                if (ox < OWd) {
                    *(u64*)(orow + ox) = acc[j][p];
                }
            }
        }
    }
}

extern "C" void kernel_launch(void* const* d_in, const int* in_sizes, int n_in,
                              void* d_out, int out_size) {
    const float* x    = (const float*)d_in[0];
    const float* wt   = (const float*)d_in[1];
    const float* bias = (const float*)d_in[2];
    float* out        = (float*)d_out;

    // Build (w,w) u64 pairs in __constant__ memory (async D2D, graph-capturable).
    void* cw_addr = nullptr;
    cudaGetSymbolAddress(&cw_addr, c_w2);
    cudaMemcpy2DAsync(cw_addr, 8, wt, 4, 4, KHd * KWd,
                      cudaMemcpyDeviceToDevice, 0);
    cudaMemcpy2DAsync((char*)cw_addr + 4, 8, wt, 4, 4, KHd * KWd,
                      cudaMemcpyDeviceToDevice, 0);

    dim3 grid((OWd + BXo - 1) / BXo, (OHd + BYo - 1) / BYo);  // (32, 64)
    conv2d_f32x2_kernel<<<grid, 256>>>(x, bias, out);
}